// round 10
// baseline (speedup 1.0000x reference)
#include <cuda_runtime.h>
#include <cuda_fp16.h>
#include <cstdint>

// VanillaRNN via warp-level HMMA, fp16 3-pass hi/lo split.
// R10: two independent batch half-groups (cols 0-7 / 8-15) phase-shifted by
// half a step, so each group's tanh epilogue overlaps the other group's MMA
// sweep. n8 B operands (ldmatrix.x2); A_lo ksteps 0-7 register-resident.

#define BATCH 2048
#define SEQT  512
#define HDIM  256
#define NCOL  16
#define NBLK  128
#define NTHR  256
#define NSTEPS 510
#define SCALE   256.0f
#define INVSCALE 0.00390625f

// smem byte offsets
#define SM_W    0          // init: W_hi staging; steady: W_lo*2^8 [256 rows][512B]
#define SM_BA   131072     // h_A: hi 4K | lo 4K (single-buffered)
#define SM_BB   139264     // h_B: hi 4K | lo 4K
#define SM_XR   147456     // 2 slots x 16 f32
#define SM_BIAS 147584     // [16][256] f32
#define SM_TOTAL 163968

__device__ __forceinline__ uint32_t s2u(const void* p) {
    uint32_t a;
    asm("{ .reg .u64 t; cvta.to.shared.u64 t, %1; cvt.u32.u64 %0, t; }" : "=r"(a) : "l"(p));
    return a;
}

#define LDSM4(r, a)                                                               \
    asm volatile("ldmatrix.sync.aligned.m8n8.x4.shared.b16 {%0,%1,%2,%3}, [%4];"  \
                 : "=r"((r)[0]), "=r"((r)[1]), "=r"((r)[2]), "=r"((r)[3])         \
                 : "r"(a))
#define LDSM2(r, a)                                                               \
    asm volatile("ldmatrix.sync.aligned.m8n8.x2.shared.b16 {%0,%1}, [%2];"        \
                 : "=r"((r)[0]), "=r"((r)[1])                                     \
                 : "r"(a))

__device__ __forceinline__ void mma_f32(float* d, const uint32_t* a,
                                        uint32_t b0, uint32_t b1) {
    asm volatile("mma.sync.aligned.m16n8k16.row.col.f32.f16.f16.f32 "
                 "{%0,%1,%2,%3}, {%4,%5,%6,%7}, {%8,%9}, {%0,%1,%2,%3};"
                 : "+f"(d[0]), "+f"(d[1]), "+f"(d[2]), "+f"(d[3])
                 : "r"(a[0]), "r"(a[1]), "r"(a[2]), "r"(a[3]), "r"(b0), "r"(b1));
}
__device__ __forceinline__ void mma_f16(uint32_t* d, const uint32_t* a,
                                        uint32_t b0, uint32_t b1) {
    asm volatile("mma.sync.aligned.m16n8k16.row.col.f16.f16.f16.f16 "
                 "{%0,%1}, {%2,%3,%4,%5}, {%6,%7}, {%0,%1};"
                 : "+r"(d[0]), "+r"(d[1])
                 : "r"(a[0]), "r"(a[1]), "r"(a[2]), "r"(a[3]), "r"(b0), "r"(b1));
}

// one k-step of the 3-pass MMA for group G (A_lo from regs)
#define KSTEP_R(G, ks) do {                                                       \
    uint32_t _bh[2], _bl[2];                                                      \
    const uint32_t _ch = (uint32_t)(((2 * (ks) + lxB) ^ l7) << 4);                \
    LDSM2(_bh, rowB##G + _ch);                                                    \
    LDSM2(_bl, rowB##G + 4096 + _ch);                                             \
    mma_f32(&d##G[0], ahi0[ks], _bh[0], _bh[1]);                                  \
    mma_f32(&d##G[4], ahi1[ks], _bh[0], _bh[1]);                                  \
    mma_f16(c##G + 0, alr[ks][0], _bh[0], _bh[1]);                                \
    mma_f16(c##G + 0, ahi0[ks],   _bl[0], _bl[1]);                                \
    mma_f16(c##G + 2, alr[ks][1], _bh[0], _bh[1]);                                \
    mma_f16(c##G + 2, ahi1[ks],   _bl[0], _bl[1]);                                \
} while (0)

// one k-step, A_lo streamed from smem (ks 8..15)
#define KSTEP_S(G, ks) do {                                                       \
    uint32_t _bh[2], _bl[2], _al0[4], _al1[4];                                    \
    const uint32_t _ch  = (uint32_t)(((2 * (ks) + lxB) ^ l7) << 4);               \
    const uint32_t _cha = (uint32_t)(((2 * (ks) + lx) ^ l7) << 4);                \
    LDSM4(_al0, rowAL0 + _cha);                                                   \
    LDSM4(_al1, rowAL1 + _cha);                                                   \
    LDSM2(_bh, rowB##G + _ch);                                                    \
    LDSM2(_bl, rowB##G + 4096 + _ch);                                             \
    mma_f32(&d##G[0], ahi0[ks], _bh[0], _bh[1]);                                  \
    mma_f32(&d##G[4], ahi1[ks], _bh[0], _bh[1]);                                  \
    mma_f16(c##G + 0, _al0,     _bh[0], _bh[1]);                                  \
    mma_f16(c##G + 0, ahi0[ks], _bl[0], _bl[1]);                                  \
    mma_f16(c##G + 2, _al1,     _bh[0], _bh[1]);                                  \
    mma_f16(c##G + 2, ahi1[ks], _bl[0], _bl[1]);                                  \
} while (0)

// epilogue stages for group G (pre -> exp -> rcp -> store+reinit)
#define EPI_S1(G, XOFF)                                                           \
    float pre##G[8];                                                              \
    {                                                                             \
        float2 _c01 = __half22float2(*(__half2*)&c##G[0]);                        \
        float2 _c23 = __half22float2(*(__half2*)&c##G[1]);                        \
        float2 _e01 = __half22float2(*(__half2*)&c##G[2]);                        \
        float2 _e23 = __half22float2(*(__half2*)&c##G[3]);                        \
        float _lov[8] = {_c01.x, _c01.y, _c23.x, _c23.y,                          \
                         _e01.x, _e01.y, _e23.x, _e23.y};                         \
        _Pragma("unroll") for (int _q = 0; _q < 8; _q++) {                        \
            int _tm = _q >> 2, _e = _q & 3;                                       \
            int _n = lr + (_e & 1);                                               \
            float _xv = *(const float*)(smc + (XOFF) + _n * 4);                   \
            pre##G[_q] = fmaf(wx[_tm * 2 + (_e >> 1)], _xv,                       \
                              fmaf(_lov[_q], INVSCALE, d##G[_q]));                \
        }                                                                         \
    }
#define EPI_S2(G)                                                                 \
    float ev##G[8];                                                               \
    _Pragma("unroll") for (int _q = 0; _q < 8; _q++)                              \
        ev##G[_q] = __expf(2.0f * pre##G[_q]);
#define EPI_S3(G)                                                                 \
    float hv##G[8];                                                               \
    _Pragma("unroll") for (int _q = 0; _q < 8; _q++)                              \
        hv##G[_q] = 1.0f - __fdividef(2.0f, ev##G[_q] + 1.0f);
#define EPI_S4(G, SBASE, BQ)                                                      \
    _Pragma("unroll") for (int _q = 0; _q < 8; _q++) {                            \
        int _tm = _q >> 2, _e = _q & 3;                                           \
        int _m = m0 + 16 * _tm + lq + ((_e >> 1) ? 8 : 0);                        \
        int _n = lr + (_e & 1);                                                   \
        __half _hi = __float2half_rn(hv##G[_q]);                                  \
        __half _lo = __float2half_rn((hv##G[_q] - __half2float(_hi)) * SCALE);    \
        uint32_t _off = (uint32_t)_n * 512 +                                      \
                        ((((uint32_t)_m >> 3) ^ (_n & 7)) << 4) + (_m & 7) * 2;   \
        *(__half*)(smc + (SBASE) + _off) = _hi;                                   \
        *(__half*)(smc + (SBASE) + 4096 + _off) = _lo;                            \
        d##G[_q] = *(const float*)(smc + SM_BIAS + (((BQ) + _q) * 256 + tid) * 4);\
    }                                                                             \
    c##G[0] = c##G[1] = c##G[2] = c##G[3] = 0u;

__global__ void __launch_bounds__(NTHR, 1) VanillaRNN_54984171323420_kernel(
    const float* __restrict__ x,    // [2048, 512]
    const float* __restrict__ Whx,  // [256, 1]
    const float* __restrict__ Whh,  // [256, 256]
    const float* __restrict__ Wph,  // [10, 256]
    const float* __restrict__ bh,   // [256, 2048]
    const float* __restrict__ bp,   // [10, 2048]
    float* __restrict__ out)        // [2048, 10]
{
    extern __shared__ char smc[];
    const uint32_t sb = s2u(smc);
    const int tid = threadIdx.x;
    const int w = tid >> 5;          // warp 0..7 -> m rows [32w, 32w+32)
    const int l = tid & 31;
    const int lq = l >> 2;
    const int lr = (l & 3) * 2;
    const int lx  = l >> 4;          // for LDSM4 A addressing
    const int lxB = (l >> 3) & 1;    // for LDSM2 B addressing
    const int l7 = l & 7;
    const int m0 = 32 * w;
    const int j0 = blockIdx.x * NCOL;

    // ---------------- stage W_hi into smem + x loads ----------------
    for (int idx = tid; idx < HDIM * HDIM; idx += NTHR) {
        int m = idx >> 8, k = idx & 255;
        __half hi = __float2half_rn(Whh[idx]);
        uint32_t ch = (uint32_t)(((k >> 3) ^ (m & 7)) << 4);
        *(__half*)(smc + SM_W + m * 512 + ch + (k & 7) * 2) = hi;
    }
    if (tid < NCOL) {
        const float* xr = x + (j0 + tid) * SEQT;
        *(float*)(smc + SM_XR + tid * 4) = xr[0];        // slot0 = x_0
        *(float*)(smc + SM_XR + 64 + tid * 4) = xr[1];   // slot1 = x_1
    }
    __syncthreads();

    // ---------------- A_hi fragments -> registers ----------------
    const uint32_t rowAL0 = sb + SM_W + (uint32_t)(m0 + (l & 15)) * 512;
    const uint32_t rowAL1 = rowAL0 + 16 * 512;
    uint32_t ahi0[16][4], ahi1[16][4];
#pragma unroll
    for (int ks = 0; ks < 16; ks++) {
        const uint32_t ch = (uint32_t)(((2 * ks + lx) ^ l7) << 4);
        LDSM4(ahi0[ks], rowAL0 + ch);
        LDSM4(ahi1[ks], rowAL1 + ch);
    }
    __syncthreads();

    // ---------------- overwrite staging with W_lo * 2^8 + bias setup ----------
    for (int idx = tid; idx < HDIM * HDIM; idx += NTHR) {
        int m = idx >> 8, k = idx & 255;
        float wv = Whh[idx];
        __half hi = __float2half_rn(wv);
        __half lo = __float2half_rn((wv - __half2float(hi)) * SCALE);
        uint32_t ch = (uint32_t)(((k >> 3) ^ (m & 7)) << 4);
        *(__half*)(smc + SM_W + m * 512 + ch + (k & 7) * 2) = lo;
    }
    float wx[4];
#pragma unroll
    for (int tm = 0; tm < 2; tm++) {
        wx[tm * 2 + 0] = Whx[m0 + 16 * tm + lq];
        wx[tm * 2 + 1] = Whx[m0 + 16 * tm + lq + 8];
#pragma unroll
        for (int g = 0; g < 2; g++)
#pragma unroll
            for (int e = 0; e < 4; e++) {
                int m = m0 + 16 * tm + lq + ((e >> 1) ? 8 : 0);
                int n = 8 * g + lr + (e & 1);
                int q = g * 8 + tm * 4 + e;
                *(float*)(smc + SM_BIAS + (q * 256 + tid) * 4) = bh[m * BATCH + j0 + n];
            }
    }
    __syncthreads();

    // ---------------- A_lo fragments for ksteps 0..7 -> registers ----------------
    uint32_t alr[8][2][4];
#pragma unroll
    for (int ks = 0; ks < 8; ks++) {
        const uint32_t ch = (uint32_t)(((2 * ks + lx) ^ l7) << 4);
        LDSM4(alr[ks][0], rowAL0 + ch);
        LDSM4(alr[ks][1], rowAL1 + ch);
    }

    // ---------------- accumulator + state init; prologue h_A(1) ----------------
    float dA[8], dB[8];
    uint32_t cA[4], cB[4];
#pragma unroll
    for (int q = 0; q < 8; q++) {
        dA[q] = *(const float*)(smc + SM_BIAS + (q * 256 + tid) * 4);
        dB[q] = *(const float*)(smc + SM_BIAS + ((8 + q) * 256 + tid) * 4);
    }
    cA[0] = cA[1] = cA[2] = cA[3] = 0u;
    cB[0] = cB[1] = cB[2] = cB[3] = 0u;
#pragma unroll
    for (int q = 0; q < 8; q++) {      // h_A(1) = tanh(b + wx*x_0) -> SM_BA
        int tm = q >> 2, e = q & 3;
        int m = m0 + 16 * tm + lq + ((e >> 1) ? 8 : 0);
        int n = lr + (e & 1);
        float xv = *(const float*)(smc + SM_XR + n * 4);
        float ev = __expf(2.0f * dA[q] + 2.0f * wx[tm * 2 + (e >> 1)] * xv);
        float h = 1.0f - __fdividef(2.0f, ev + 1.0f);
        __half hi = __float2half_rn(h);
        __half lo = __float2half_rn((h - __half2float(hi)) * SCALE);
        uint32_t off = (uint32_t)n * 512 + ((((uint32_t)m >> 3) ^ (n & 7)) << 4) + (m & 7) * 2;
        *(__half*)(smc + SM_BA + off) = hi;
        *(__half*)(smc + SM_BA + 4096 + off) = lo;
    }
    __syncthreads();

    const uint32_t rowBA = sb + SM_BA + (uint32_t)l7 * 512;
    const uint32_t rowBB = sb + SM_BB + (uint32_t)l7 * 512;

    // ================= recurrence: 510 steps, 2 phases each =================
#pragma unroll 1
    for (int it = 1; it <= NSTEPS; it++) {
        const int p = it & 1;
        float xnext = 0.0f;
        if (tid < NCOL) xnext = x[(j0 + tid) * SEQT + it + 1];

        // ---- phase 1: MMA_A(it) interleaved with epilogue_B(it-1) ----
        KSTEP_R(A, 0);  KSTEP_R(A, 1);
        EPI_S1(B, SM_XR + (1 - p) * 64 + 32);
        KSTEP_R(A, 2);  KSTEP_R(A, 3);
        EPI_S2(B);
        KSTEP_R(A, 4);  KSTEP_R(A, 5);  KSTEP_R(A, 6);  KSTEP_R(A, 7);
        EPI_S3(B);
        KSTEP_S(A, 8);  KSTEP_S(A, 9);  KSTEP_S(A, 10); KSTEP_S(A, 11);
        EPI_S4(B, SM_BB, 8);
        KSTEP_S(A, 12); KSTEP_S(A, 13); KSTEP_S(A, 14); KSTEP_S(A, 15);
        __syncthreads();

        // ---- phase 2: MMA_B(it) interleaved with epilogue_A(it) ----
        KSTEP_R(B, 0);  KSTEP_R(B, 1);
        EPI_S1(A, SM_XR + p * 64);
        KSTEP_R(B, 2);  KSTEP_R(B, 3);
        EPI_S2(A);
        KSTEP_R(B, 4);  KSTEP_R(B, 5);  KSTEP_R(B, 6);  KSTEP_R(B, 7);
        EPI_S3(A);
        KSTEP_S(B, 8);  KSTEP_S(B, 9);  KSTEP_S(B, 10); KSTEP_S(B, 11);
        EPI_S4(A, SM_BA, 0);
        if (tid < NCOL) *(float*)(smc + SM_XR + (1 - p) * 64 + tid * 4) = xnext;
        KSTEP_S(B, 12); KSTEP_S(B, 13); KSTEP_S(B, 14); KSTEP_S(B, 15);
        __syncthreads();
    }

    // ---- peeled epilogue_B(510): h_B(511) (x_510 is in slot0) ----
    {
        EPI_S1(B, SM_XR + 0 * 64 + 32);
        EPI_S2(B);
        EPI_S3(B);
        EPI_S4(B, SM_BB, 8);
    }
    __syncthreads();

    // ================= projection: out = Wph @ h + bp =================
    if (tid < 10 * NCOL) {
        const int c = tid >> 4, j = tid & 15;
        const int nl = j & 7;
        const uint32_t base = (j < 8) ? SM_BA : SM_BB;
        float s = bp[c * BATCH + j0 + j];
        const float* wr = Wph + c * HDIM;
#pragma unroll 8
        for (int k = 0; k < HDIM; k++) {
            uint32_t off = (uint32_t)nl * 512 + ((((uint32_t)k >> 3) ^ (nl & 7)) << 4) + (k & 7) * 2;
            float hvv = __half2float(*(__half*)(smc + base + off)) +
                        __half2float(*(__half*)(smc + base + 4096 + off)) * INVSCALE;
            s = fmaf(wr[k], hvv, s);
        }
        out[(j0 + j) * 10 + c] = s;
    }
}

extern "C" void kernel_launch(void* const* d_in, const int* in_sizes, int n_in,
                              void* d_out, int out_size) {
    const float* x   = (const float*)d_in[0];
    const float* Whx = (const float*)d_in[1];
    const float* Whh = (const float*)d_in[2];
    const float* Wph = (const float*)d_in[3];
    const float* bh  = (const float*)d_in[4];
    const float* bp  = (const float*)d_in[5];
    float* out = (float*)d_out;

    cudaFuncSetAttribute(VanillaRNN_54984171323420_kernel,
                         cudaFuncAttributeMaxDynamicSharedMemorySize, SM_TOTAL);
    VanillaRNN_54984171323420_kernel<<<NBLK, NTHR, SM_TOTAL>>>(
        x, Whx, Whh, Wph, bh, bp, out);
}